// round 16
// baseline (speedup 1.0000x reference)
#include <cuda_runtime.h>
#include <cuda_fp16.h>
#include <cstdint>

// ---------------------------------------------------------------------------
// Problem constants
// ---------------------------------------------------------------------------
#define BB    16
#define SS    2048
#define NN1   257
#define EE    4096
#define HH    512
#define LDD   16
#define ETRD  768
#define DD    528
#define DDP   576
#define NCLS  3
#define NLAY  2

#define MM    (BB*NN1)
#define XSZ   (BB*NN1*DD)
#define DEGSZ (NCLS*BB*NN1)
#define CBSZ  (NCLS*BB)
#define HWSZ  (BB*NN1*3)

// ---------------------------------------------------------------------------
// Device scratch
// ---------------------------------------------------------------------------
__device__ float  g_x0 [XSZ];
__device__ __half g_x0h[MM*DDP];
__device__ __half g_hc [NCLS*MM*DDP];
__device__ __half g_xb16[NCLS*MM*DDP];
__device__ float  g_deg[DEGSZ];
__device__ int    g_off[CBSZ*(NN1+1)];
__device__ int    g_cur[CBSZ*NN1];
__device__ int    g_esrc[CBSZ*EE];
__device__ float  g_ecoef[CBSZ*EE];
__device__ __half g_embh[BB*SS*ETRD];
__device__ __half g_Wt [HH*ETRD];
__device__ __half g_Wg [NCLS*NLAY*DD*DDP];
__device__ float  g_Who[DD*3];
__device__ float  g_Wto[DD*3];
__device__ float  g_bho[3];
__device__ float  g_bto[3];
__device__ float  g_hW [HWSZ];
__device__ float  g_hT [HWSZ];

// ---------------------------------------------------------------------------
// mma / ldmatrix / cp.async helpers
// ---------------------------------------------------------------------------
__device__ __forceinline__ void mma_f16(float* c, const uint32_t* a, const uint32_t* b) {
    asm volatile(
        "mma.sync.aligned.m16n8k16.row.col.f32.f16.f16.f32 "
        "{%0,%1,%2,%3}, {%4,%5,%6,%7}, {%8,%9}, {%0,%1,%2,%3};"
        : "+f"(c[0]), "+f"(c[1]), "+f"(c[2]), "+f"(c[3])
        : "r"(a[0]), "r"(a[1]), "r"(a[2]), "r"(a[3]), "r"(b[0]), "r"(b[1]));
}

__device__ __forceinline__ void ldsm4(uint32_t* r, uint32_t saddr) {
    asm volatile("ldmatrix.sync.aligned.m8n8.x4.shared.b16 {%0,%1,%2,%3}, [%4];"
                 : "=r"(r[0]), "=r"(r[1]), "=r"(r[2]), "=r"(r[3]) : "r"(saddr));
}

__device__ __forceinline__ uint32_t s2u(const void* p) {
    return (uint32_t)__cvta_generic_to_shared(p);
}

__device__ __forceinline__ void cp16(uint32_t s, const void* g) {
    asm volatile("cp.async.cg.shared.global [%0], [%1], 16;" :: "r"(s), "l"(g));
}
#define CP_COMMIT() asm volatile("cp.async.commit_group;" ::: "memory")
#define CP_WAIT0()  asm volatile("cp.async.wait_group 0;"  ::: "memory")

__device__ __forceinline__ uint32_t pack_h2(float x, float y) {
    __half2 h = __floats2half2_rn(x, y);
    return *(uint32_t*)&h;
}

// ---------------------------------------------------------------------------
// Small helper kernels
// ---------------------------------------------------------------------------
__global__ void k_initmisc(float* __restrict__ deg,
                           float* __restrict__ hW,
                           float* __restrict__ hT) {
    int t = blockIdx.x * blockDim.x + threadIdx.x;
    if (t < DEGSZ) deg[t] = 1.f;
    if (t < HWSZ) { hW[t] = 0.f; hT[t] = 0.f; }
}

__global__ void k_initx0(float* __restrict__ x0,
                         const int* __restrict__ entLab,
                         const float* __restrict__ tbl) {
    int t = blockIdx.x * blockDim.x + threadIdx.x;
    if (t >= XSZ) return;
    int r = t / DD, c = t % DD;
    float v = 0.f;
    if (c < LDD) {
        int i = r % NN1, b = r / NN1;
        if (i == 0) v = tbl[c];
        else {
            int lbl = entLab[b*(NN1-1) + i - 1];
            v = lbl ? tbl[lbl*LDD + c] : 0.f;
        }
    }
    x0[t] = v;
}

__global__ void k_eh(const float4* __restrict__ in, uint2* __restrict__ outp, int n4) {
    int i = blockIdx.x * blockDim.x + threadIdx.x;
    if (i < n4) {
        float4 v = in[i];
        uint2 u;
        u.x = pack_h2(v.x, v.y);
        u.y = pack_h2(v.z, v.w);
        outp[i] = u;
    }
}

__global__ void k_x0h(const float* __restrict__ x0, __half* __restrict__ x0h) {
    int t = blockIdx.x * blockDim.x + threadIdx.x;
    if (t >= MM*DDP) return;
    int r = t / DDP, c = t % DDP;
    x0h[t] = (c < DD) ? __float2half_rn(x0[(size_t)r*DD + c]) : __half(0);
}

__global__ void k_deg(float* __restrict__ deg,
                      const int* __restrict__ ei,
                      const int* __restrict__ ea) {
    int t = blockIdx.x * blockDim.x + threadIdx.x;
    if (t >= BB*EE) return;
    int b = t >> 12, e = t & (EE-1);
    int dst = ei[b*2*EE + EE + e];
    int a   = ea[b*EE + e];
    atomicAdd(&deg[(a*BB + b)*NN1 + dst], 1.f);
}

__global__ void k_off(const float* __restrict__ deg) {
    int cb   = blockIdx.x;
    int lane = threadIdx.x;
    const float* dg = deg + cb*NN1;
    int* off = g_off + cb*(NN1+1);
    int* cur = g_cur + cb*NN1;
    if (lane == 0) off[0] = 0;
    int carry = 0;
    for (int base = 0; base < NN1; base += 32) {
        int i = base + lane;
        int v = (i < NN1) ? (int)dg[i] - 1 : 0;
        int s = v;
        #pragma unroll
        for (int d = 1; d < 32; d <<= 1) {
            int t = __shfl_up_sync(0xffffffffu, s, d);
            if (lane >= d) s += t;
        }
        if (i < NN1) {
            cur[i]   = carry + s - v;
            off[i+1] = carry + s;
        }
        carry += __shfl_sync(0xffffffffu, s, 31);
    }
}

__global__ void k_scatter(const float* __restrict__ deg,
                          const int* __restrict__ ei,
                          const int* __restrict__ ea) {
    int t = blockIdx.x * blockDim.x + threadIdx.x;
    if (t >= BB*EE) return;
    int b = t >> 12, e = t & (EE-1);
    int src = ei[b*2*EE + e];
    int dst = ei[b*2*EE + EE + e];
    int a   = ea[b*EE + e];
    int cb  = a*BB + b;
    const float* dg = deg + cb*NN1;
    float coef = rsqrtf(dg[src]) * rsqrtf(dg[dst]);
    int pos = atomicAdd(&g_cur[cb*NN1 + dst], 1);
    g_esrc [cb*EE + pos] = src;
    g_ecoef[cb*EE + pos] = coef;
}

__global__ void k_th(const float* __restrict__ W, __half* __restrict__ Wt,
                     int K, int N, int KP) {
    const float* Wz  = W  + (size_t)blockIdx.z*K*N;
    __half*      Wtz = Wt + (size_t)blockIdx.z*N*KP;
    __shared__ float t[32][33];
    int k = blockIdx.x*32 + threadIdx.y;
    int n = blockIdx.y*32 + threadIdx.x;
    if (k < K && n < N) t[threadIdx.y][threadIdx.x] = Wz[(size_t)k*N + n];
    __syncthreads();
    int no = blockIdx.y*32 + threadIdx.y;
    int ko = blockIdx.x*32 + threadIdx.x;
    if (no < N && ko < KP)
        Wtz[(size_t)no*KP + ko] = (ko < K) ? __float2half_rn(t[threadIdx.x][threadIdx.y])
                                           : __half(0);
}

// ---------------------------------------------------------------------------
// Big fp16 GEMM (with y-base for split launch), cp.async + LDSM
// ---------------------------------------------------------------------------
#define KC    64
#define RA_LD 72
#define R_SZH (128*RA_LD)
#define RED_SMEM (4*R_SZH*2)

__global__ void __launch_bounds__(512, 1) k_mma_red(
    const __half* __restrict__ A,
    const __half* __restrict__ Bt,
    const float*  __restrict__ bias,
    const int*    __restrict__ entIdx,
    float*        __restrict__ x0,
    int yBase)
{
    extern __shared__ __align__(16) __half smh[];
    __half* sAb[2] = { smh,            smh + R_SZH };
    __half* sBb[2] = { smh + 2*R_SZH,  smh + 3*R_SZH };

    const int tid  = threadIdx.x;
    const int lane = tid & 31;
    const int wid  = tid >> 5;
    const int gr   = lane >> 2;
    const int kq   = lane & 3;
    const int wm   = wid & 3;
    const int wn   = wid >> 2;
    const int row0 = (yBase + blockIdx.y) * 128;
    const int col0 = blockIdx.x * 128;

    const int sr = tid >> 2;
    const int sg = tid & 3;

    const int arow_l = ((lane >> 3) & 1)*8 + (lane & 7);
    const int acol_l = (lane >> 4)*8;
    const int brow_l = (lane >> 4)*8 + (lane & 7);
    const int bcol_l = ((lane >> 3) & 1)*8;
    uint32_t aoff[2], boff[2];
    #pragma unroll
    for (int mi = 0; mi < 2; mi++)
        aoff[mi] = ((wm*32 + mi*16 + arow_l)*RA_LD + acol_l)*2;
    #pragma unroll
    for (int pr = 0; pr < 2; pr++)
        boff[pr] = ((wn*32 + pr*16 + brow_l)*RA_LD + bcol_l)*2;
    uint32_t sAu[2] = { s2u(sAb[0]), s2u(sAb[1]) };
    uint32_t sBu[2] = { s2u(sBb[0]), s2u(sBb[1]) };

    float acc[2][4][4];
    #pragma unroll
    for (int i = 0; i < 2; i++)
        #pragma unroll
        for (int j = 0; j < 4; j++)
            #pragma unroll
            for (int u = 0; u < 4; u++) acc[i][j][u] = 0.f;

    const __half* agp = A  + (size_t)(row0 + sr)*ETRD + sg*16;
    const __half* bgp = Bt + (size_t)(col0 + sr)*ETRD + sg*16;
    const uint32_t sAoff = (sr*RA_LD + sg*16)*2;

    auto ldchunk = [&](int k0, int buf) {
        cp16(sAu[buf] + sAoff,      agp + k0);
        cp16(sAu[buf] + sAoff + 16, agp + k0 + 8);
        cp16(sBu[buf] + sAoff,      bgp + k0);
        cp16(sBu[buf] + sAoff + 16, bgp + k0 + 8);
        CP_COMMIT();
    };
    auto compute = [&](int buf) {
        #pragma unroll
        for (int ks = 0; ks < KC/16; ks++) {
            uint32_t af[2][4], bf[2][4];
            ldsm4(af[0], sAu[buf] + aoff[0] + ks*32);
            ldsm4(af[1], sAu[buf] + aoff[1] + ks*32);
            ldsm4(bf[0], sBu[buf] + boff[0] + ks*32);
            ldsm4(bf[1], sBu[buf] + boff[1] + ks*32);
            #pragma unroll
            for (int mi = 0; mi < 2; mi++) {
                mma_f16(acc[mi][0], af[mi], &bf[0][0]);
                mma_f16(acc[mi][1], af[mi], &bf[0][2]);
                mma_f16(acc[mi][2], af[mi], &bf[1][0]);
                mma_f16(acc[mi][3], af[mi], &bf[1][2]);
            }
        }
    };

    ldchunk(0, 0);
    CP_WAIT0();
    __syncthreads();
    #pragma unroll 1
    for (int ch = 0; ch < ETRD/KC; ch++) {
        if (ch + 1 < ETRD/KC) ldchunk((ch + 1)*KC, (ch + 1) & 1);
        compute(ch & 1);
        if (ch + 1 < ETRD/KC) {
            CP_WAIT0();
            __syncthreads();
        }
    }

    int    nodev[2][2];
    float* basep[2][2];
    #pragma unroll
    for (int mi = 0; mi < 2; mi++)
        #pragma unroll
        for (int h = 0; h < 2; h++) {
            int r  = row0 + wm*32 + mi*16 + gr + h*8;
            int nd = entIdx[r];
            nodev[mi][h] = nd;
            int b = r >> 11;
            basep[mi][h] = x0 + ((size_t)(b*NN1 + nd))*DD + LDD;
        }
    #pragma unroll
    for (int ni = 0; ni < 4; ni++) {
        int c = col0 + wn*32 + ni*8 + kq*2;
        float b0 = __ldg(bias + c), b1 = __ldg(bias + c + 1);
        #pragma unroll
        for (int mi = 0; mi < 2; mi++) {
            #pragma unroll
            for (int h = 0; h < 2; h++) {
                if (nodev[mi][h] == 0) continue;
                float v0 = acc[mi][ni][2*h    ] + b0;
                float v1 = acc[mi][ni][2*h + 1] + b1;
                if (v0 > 0.f) atomicMax((int*)(basep[mi][h] + c),     __float_as_int(v0));
                if (v1 > 0.f) atomicMax((int*)(basep[mi][h] + c + 1), __float_as_int(v1));
            }
        }
    }
}

// ---------------------------------------------------------------------------
// xW GEMM, full cp.async + LDSM, 3 classes via grid.z
// ---------------------------------------------------------------------------
__global__ void __launch_bounds__(512, 1) k_mma_xw(
    const __half* __restrict__ Abase,
    const __half* __restrict__ Wg,
    __half*       __restrict__ Cbase,
    int M, long long strideA, int layer)
{
    const int z = blockIdx.z;
    const __half* A  = Abase + (size_t)z*strideA;
    const __half* Bt = Wg + ((size_t)z*NLAY + layer)*DD*DDP;
    __half* C = Cbase + (size_t)z*MM*DDP;

    extern __shared__ __align__(16) __half smh[];
    __half* sAb[2] = { smh,            smh + R_SZH };
    __half* sBb[2] = { smh + 2*R_SZH,  smh + 3*R_SZH };

    const int tid  = threadIdx.x;
    const int lane = tid & 31;
    const int wid  = tid >> 5;
    const int gr   = lane >> 2;
    const int kq   = lane & 3;
    const int wm   = wid & 3;
    const int wn   = wid >> 2;
    const int row0 = blockIdx.y * 128;
    const int col0 = blockIdx.x * 128;

    const int sr = tid >> 2;
    const int sg = tid & 3;

    const int arow_l = ((lane >> 3) & 1)*8 + (lane & 7);
    const int acol_l = (lane >> 4)*8;
    const int brow_l = (lane >> 4)*8 + (lane & 7);
    const int bcol_l = ((lane >> 3) & 1)*8;
    uint32_t aoff[2], boff[2];
    #pragma unroll
    for (int mi = 0; mi < 2; mi++)
        aoff[mi] = ((wm*32 + mi*16 + arow_l)*RA_LD + acol_l)*2;
    #pragma unroll
    for (int pr = 0; pr < 2; pr++)
        boff[pr] = ((wn*32 + pr*16 + brow_l)*RA_LD + bcol_l)*2;
    uint32_t sAu[2] = { s2u(sAb[0]), s2u(sAb[1]) };
    uint32_t sBu[2] = { s2u(sBb[0]), s2u(sBb[1]) };

    float acc[2][4][4];
    #pragma unroll
    for (int i = 0; i < 2; i++)
        #pragma unroll
        for (int j = 0; j < 4; j++)
            #pragma unroll
            for (int u = 0; u < 4; u++) acc[i][j][u] = 0.f;

    int arow = row0 + sr; if (arow >= M)  arow = M - 1;
    int brow = col0 + sr; if (brow >= DD) brow = DD - 1;
    const __half* agp = A  + (size_t)arow*DDP + sg*16;
    const __half* bgp = Bt + (size_t)brow*DDP + sg*16;
    const uint32_t sAoff = (sr*RA_LD + sg*16)*2;

    auto ldchunk = [&](int k0, int buf) {
        cp16(sAu[buf] + sAoff,      agp + k0);
        cp16(sAu[buf] + sAoff + 16, agp + k0 + 8);
        cp16(sBu[buf] + sAoff,      bgp + k0);
        cp16(sBu[buf] + sAoff + 16, bgp + k0 + 8);
        CP_COMMIT();
    };
    auto compute = [&](int buf) {
        #pragma unroll
        for (int ks = 0; ks < KC/16; ks++) {
            uint32_t af[2][4], bf[2][4];
            ldsm4(af[0], sAu[buf] + aoff[0] + ks*32);
            ldsm4(af[1], sAu[buf] + aoff[1] + ks*32);
            ldsm4(bf[0], sBu[buf] + boff[0] + ks*32);
            ldsm4(bf[1], sBu[buf] + boff[1] + ks*32);
            #pragma unroll
            for (int mi = 0; mi < 2; mi++) {
                mma_f16(acc[mi][0], af[mi], &bf[0][0]);
                mma_f16(acc[mi][1], af[mi], &bf[0][2]);
                mma_f16(acc[mi][2], af[mi], &bf[1][0]);
                mma_f16(acc[mi][3], af[mi], &bf[1][2]);
            }
        }
    };

    ldchunk(0, 0);
    CP_WAIT0();
    __syncthreads();
    #pragma unroll 1
    for (int ch = 0; ch < DDP/KC; ch++) {
        if (ch + 1 < DDP/KC) ldchunk((ch + 1)*KC, (ch + 1) & 1);
        compute(ch & 1);
        if (ch + 1 < DDP/KC) {
            CP_WAIT0();
            __syncthreads();
        }
    }

    #pragma unroll
    for (int mi = 0; mi < 2; mi++) {
        #pragma unroll
        for (int h = 0; h < 2; h++) {
            int gm = row0 + wm*32 + mi*16 + gr + h*8;
            if (gm >= M) continue;
            #pragma unroll
            for (int ni = 0; ni < 4; ni++) {
                int gn = col0 + wn*32 + ni*8 + kq*2;
                if (gn < DD) {
                    *(uint32_t*)(C + (size_t)gm*DDP + gn) =
                        pack_h2(acc[mi][ni][2*h], acc[mi][ni][2*h + 1]);
                }
            }
        }
    }
}

// ---------------------------------------------------------------------------
// Sparse GCN aggregation, warp-per-dst (8 dst/block), fp16 h, grid.z classes.
// ---------------------------------------------------------------------------
#define NH2  (DD/2)     // 264
#define NH2P (DDP/2)    // 288

__global__ void __launch_bounds__(256) k_spmm(
    const __half* __restrict__ hbase,
    __half* __restrict__ xbH,
    const float* __restrict__ deg,
    const float* __restrict__ bgcn,
    const float* __restrict__ Who,
    const float* __restrict__ Wto,
    float* __restrict__ hW,
    float* __restrict__ hT,
    int layer)
{
    int wid  = threadIdx.x >> 5;
    int lane = threadIdx.x & 31;
    int dst  = blockIdx.x*8 + wid;
    if (dst >= NN1) return;
    int b   = blockIdx.y;
    int cls = blockIdx.z;
    int cb  = cls*BB + b;

    const float* bias = bgcn + (size_t)(cls*NLAY + layer)*DD;
    const __half* hb  = hbase + ((size_t)cls*MM + (size_t)b*NN1)*DDP;

    const int* off = g_off + cb*(NN1+1);
    int e0 = off[dst], e1 = off[dst+1];
    const int*   es = g_esrc  + cb*EE;
    const float* ec = g_ecoef + cb*EE;

    float2 acc[9];
    #pragma unroll
    for (int it = 0; it < 9; it++) acc[it] = make_float2(0.f, 0.f);

    for (int e = e0; e < e1; e++) {
        int   src = es[e];
        float w   = ec[e];
        const __half2* hr = (const __half2*)(hb + (size_t)src*DDP);
        #pragma unroll
        for (int it = 0; it < 9; it++) {
            int j = lane + it*32;
            if (j < NH2) {
                float2 x = __half22float2(hr[j]);
                acc[it].x += w * x.x;
                acc[it].y += w * x.y;
            }
        }
    }

    float dinv = 1.f / deg[cb*NN1 + dst];
    const __half2* hd = (const __half2*)(hb + (size_t)dst*DDP);

    float2 v[9];
    #pragma unroll
    for (int it = 0; it < 9; it++) {
        int j = lane + it*32;
        if (j < NH2) {
            float2 s = __half22float2(hd[j]);
            float2 bi = *(const float2*)(bias + 2*j);
            v[it].x = acc[it].x + s.x*dinv + bi.x;
            v[it].y = acc[it].y + s.y*dinv + bi.y;
        } else {
            v[it] = make_float2(0.f, 0.f);
        }
    }

    if (layer == 0) {
        __half* xo = xbH + ((size_t)cls*MM + (size_t)b*NN1 + dst)*DDP;
        #pragma unroll
        for (int it = 0; it < 9; it++) {
            int j = lane + it*32;
            *(uint32_t*)(xo + 2*j) = pack_h2(v[it].x, v[it].y);
        }
        return;
    }

    float lw[3] = {0.f, 0.f, 0.f}, lt[3] = {0.f, 0.f, 0.f};
    #pragma unroll
    for (int it = 0; it < 9; it++) {
        int j = lane + it*32;
        if (j < NH2) {
            #pragma unroll
            for (int c = 0; c < 3; c++) {
                lw[c] += v[it].x*Who[(2*j)*3 + c] + v[it].y*Who[(2*j + 1)*3 + c];
                lt[c] += v[it].x*Wto[(2*j)*3 + c] + v[it].y*Wto[(2*j + 1)*3 + c];
            }
        }
    }
    #pragma unroll
    for (int d = 16; d > 0; d >>= 1) {
        #pragma unroll
        for (int c = 0; c < 3; c++) {
            lw[c] += __shfl_down_sync(0xffffffffu, lw[c], d);
            lt[c] += __shfl_down_sync(0xffffffffu, lt[c], d);
        }
    }
    if (lane == 0) {
        int idx = (b*NN1 + dst)*3;
        #pragma unroll
        for (int c = 0; c < 3; c++) {
            atomicAdd(&hW[idx + c], lw[c] * (1.f/3.f));
            atomicAdd(&hT[idx + c], lt[c] * (1.f/3.f));
        }
    }
}

// ---------------------------------------------------------------------------
// Collapsed head/tail weights + logits
// ---------------------------------------------------------------------------
__global__ void k_ho(const float* __restrict__ W_head, const float* __restrict__ W_tail,
                     const float* __restrict__ W_out,
                     const float* __restrict__ b_head, const float* __restrict__ b_tail,
                     float* __restrict__ Who, float* __restrict__ Wto,
                     float* __restrict__ bho, float* __restrict__ bto) {
    int t = blockIdx.x * blockDim.x + threadIdx.x;
    if (t < 2*DD*3) {
        int which = t / (DD*3), rc = t % (DD*3), r = rc / 3, c = rc % 3;
        const float* W = which ? W_tail : W_head;
        float acc = 0.f;
        for (int j = 0; j < DD; j++) acc += W[r*DD + j] * W_out[j*3 + c];
        (which ? Wto : Who)[r*3 + c] = acc;
    } else if (t < 2*DD*3 + 6) {
        int u = t - 2*DD*3, which = u / 3, c = u % 3;
        const float* bb = which ? b_tail : b_head;
        float acc = 0.f;
        for (int j = 0; j < DD; j++) acc += bb[j] * W_out[j*3 + c];
        (which ? bto : bho)[c] = acc;
    }
}

__global__ void k_logits(const int* __restrict__ cands,
                         const float* __restrict__ hW, const float* __restrict__ hT,
                         const float* __restrict__ bho, const float* __restrict__ bto,
                         const float* __restrict__ b_out,
                         float* __restrict__ out) {
    int t = blockIdx.x * blockDim.x + threadIdx.x;
    const int TOT = BB*NN1*(NN1-1)*3;
    if (t >= TOT) return;
    int c = t % 3;
    int j = (t / 3) & 255;
    int i = (t / (3*256)) % NN1;
    int b = t / (3*256*NN1);
    int m = cands[((long long)(b*NN1 + i))*NN1 + j + 1];
    float v = b_out[c];
    if (m) v += hW[(b*NN1 + i)*3 + c] + bho[c] + hT[(b*NN1 + j + 1)*3 + c] + bto[c];
    out[t] = v;
}

// ---------------------------------------------------------------------------
// Launch (multi-stream fork/join, graph-capturable)
// ---------------------------------------------------------------------------
extern "C" void kernel_launch(void* const* d_in, const int* in_sizes, int n_in,
                              void* d_out, int out_size) {
    const float* emb     = (const float*)d_in[0];
    const int*   entIdx  = (const int*)  d_in[1];
    const int*   entLab  = (const int*)  d_in[2];
    const int*   edgeIdx = (const int*)  d_in[3];
    const int*   edgeAttr= (const int*)  d_in[4];
    const int*   cands   = (const int*)  d_in[5];
    const float* W_red   = (const float*)d_in[6];
    const float* b_red   = (const float*)d_in[7];
    const float* tbl     = (const float*)d_in[8];
    const float* W_gcn   = (const float*)d_in[9];
    const float* b_gcn   = (const float*)d_in[10];
    const float* W_head  = (const float*)d_in[11];
    const float* b_head  = (const float*)d_in[12];
    const float* W_tail  = (const float*)d_in[13];
    const float* b_tail  = (const float*)d_in[14];
    const float* W_out   = (const float*)d_in[15];
    const float* b_out   = (const float*)d_in[16];
    float* out = (float*)d_out;

    static float *px0=nullptr, *pdeg,
                 *pWho, *pWto, *pbho, *pbto, *phW, *phT;
    static __half *pWt, *pWg, *pEh, *px0h, *pxb16, *phc;
    static cudaStream_t s2 = nullptr, s3 = nullptr;
    static cudaEvent_t evFork = nullptr, evJ2 = nullptr, evJ3a = nullptr, evRed2 = nullptr;
    static bool attr_set = false;
    if (!px0) {
        cudaGetSymbolAddress((void**)&px0,   g_x0);
        cudaGetSymbolAddress((void**)&px0h,  g_x0h);
        cudaGetSymbolAddress((void**)&phc,   g_hc);
        cudaGetSymbolAddress((void**)&pxb16, g_xb16);
        cudaGetSymbolAddress((void**)&pdeg,  g_deg);
        cudaGetSymbolAddress((void**)&pWt,   g_Wt);
        cudaGetSymbolAddress((void**)&pWg,   g_Wg);
        cudaGetSymbolAddress((void**)&pEh,   g_embh);
        cudaGetSymbolAddress((void**)&pWho,  g_Who);
        cudaGetSymbolAddress((void**)&pWto,  g_Wto);
        cudaGetSymbolAddress((void**)&pbho,  g_bho);
        cudaGetSymbolAddress((void**)&pbto,  g_bto);
        cudaGetSymbolAddress((void**)&phW,   g_hW);
        cudaGetSymbolAddress((void**)&phT,   g_hT);
        cudaStreamCreateWithFlags(&s2, cudaStreamNonBlocking);
        cudaStreamCreateWithFlags(&s3, cudaStreamNonBlocking);
        cudaEventCreateWithFlags(&evFork, cudaEventDisableTiming);
        cudaEventCreateWithFlags(&evJ2,   cudaEventDisableTiming);
        cudaEventCreateWithFlags(&evJ3a,  cudaEventDisableTiming);
        cudaEventCreateWithFlags(&evRed2, cudaEventDisableTiming);
    }
    if (!attr_set) {
        cudaFuncSetAttribute(k_mma_red, cudaFuncAttributeMaxDynamicSharedMemorySize, RED_SMEM);
        cudaFuncSetAttribute(k_mma_xw,  cudaFuncAttributeMaxDynamicSharedMemorySize, RED_SMEM);
        attr_set = true;
    }

    auto blocks = [](int n) { return (n + 255) / 256; };
    const int EH_TOT4  = BB*SS*ETRD/4;
    const int EH_HALF4 = EH_TOT4/2;

    // ---- fork ----
    cudaEventRecord(evFork, 0);
    cudaStreamWaitEvent(s2, evFork, 0);
    cudaStreamWaitEvent(s3, evFork, 0);

    // s2: CSR chain + Wg transpose + collapsed head/tail
    k_initmisc<<<blocks(HWSZ), 256, 0, s2>>>(pdeg, phW, phT);
    k_deg     <<<blocks(BB*EE), 256, 0, s2>>>(pdeg, edgeIdx, edgeAttr);
    k_off     <<<CBSZ, 32, 0, s2>>>(pdeg);
    k_scatter <<<blocks(BB*EE), 256, 0, s2>>>(pdeg, edgeIdx, edgeAttr);
    {
        dim3 bl(32, 32);
        k_th<<<dim3(DDP/32, (DD+31)/32, NCLS*NLAY), bl, 0, s2>>>(W_gcn, pWg, DD, DD, DDP);
    }
    k_ho<<<blocks(2*DD*3 + 6), 256, 0, s2>>>(W_head, W_tail, W_out, b_head, b_tail,
                                             pWho, pWto, pbho, pbto);
    cudaEventRecord(evJ2, s2);

    // s3: x0 init + W_red transpose, then emb half 2 convert + GEMM half 2
    // (all in-stream ordered on s3; runs concurrently with half 1 on main)
    k_initx0<<<blocks(XSZ), 256, 0, s3>>>(px0, entLab, tbl);
    {
        dim3 bl(32, 32);
        k_th<<<dim3(ETRD/32, HH/32, 1), bl, 0, s3>>>(W_red, pWt, ETRD, HH, ETRD);
    }
    cudaEventRecord(evJ3a, s3);           // x0 + Wt ready (for main's half 1)
    k_eh<<<blocks(EH_HALF4), 256, 0, s3>>>((const float4*)emb + EH_HALF4,
                                           (uint2*)pEh + EH_HALF4, EH_HALF4);
    {
        dim3 g(HH/128, 128);              // y-blocks [128,256)
        k_mma_red<<<g, 512, RED_SMEM, s3>>>(pEh, pWt, b_red, entIdx, px0, 128);
    }
    cudaEventRecord(evRed2, s3);

    // main: emb half 1 convert -> GEMM half 1 (concurrent with s3's half 2)
    k_eh<<<blocks(EH_HALF4), 256>>>((const float4*)emb, (uint2*)pEh, EH_HALF4);
    cudaStreamWaitEvent(0, evJ3a, 0);
    {
        dim3 g(HH/128, 128);              // y-blocks [0,128)
        k_mma_red<<<g, 512, RED_SMEM>>>(pEh, pWt, b_red, entIdx, px0, 0);
    }
    cudaStreamWaitEvent(0, evRed2, 0);    // join half 2 (atomics commute)
    k_x0h<<<blocks(MM*DDP), 256>>>(px0, px0h);

    cudaStreamWaitEvent(0, evJ2, 0);      // CSR, Wg, Who/Wto, hW/hT ready

    // GCN: 2 layers, all 3 classes per launch; layer 1 fuses head/tail proj
    {
        dim3 gx((DD + 127)/128, (MM + 127)/128, NCLS);
        dim3 gs((NN1 + 7)/8, BB, NCLS);
        k_mma_xw<<<gx, 512, RED_SMEM>>>(px0h, pWg, phc, MM, 0LL, 0);
        k_spmm  <<<gs, 256>>>(phc, pxb16, pdeg, b_gcn, pWho, pWto, phW, phT, 0);
        k_mma_xw<<<gx, 512, RED_SMEM>>>(pxb16, pWg, phc, MM, (long long)MM*DDP, 1);
        k_spmm  <<<gs, 256>>>(phc, nullptr, pdeg, b_gcn, pWho, pWto, phW, phT, 1);
    }

    // logits
    k_logits<<<blocks(BB*NN1*(NN1-1)*3), 256>>>(cands, phW, phT, pbho, pbto, b_out, out);
}

// round 17
// speedup vs baseline: 1.0668x; 1.0668x over previous
#include <cuda_runtime.h>
#include <cuda_fp16.h>
#include <cstdint>

// ---------------------------------------------------------------------------
// Problem constants
// ---------------------------------------------------------------------------
#define BB    16
#define SS    2048
#define NN1   257
#define EE    4096
#define HH    512
#define LDD   16
#define ETRD  768
#define DD    528
#define DDP   576
#define NCLS  3
#define NLAY  2

#define MM    (BB*NN1)
#define XSZ   (BB*NN1*DD)
#define DEGSZ (NCLS*BB*NN1)
#define CBSZ  (NCLS*BB)
#define HWSZ  (BB*NN1*3)

// ---------------------------------------------------------------------------
// Device scratch
// ---------------------------------------------------------------------------
__device__ float  g_x0 [XSZ];
__device__ __half g_x0h[MM*DDP];
__device__ __half g_hc [NCLS*MM*DDP];
__device__ __half g_xb16[NCLS*MM*DDP];
__device__ float  g_deg[DEGSZ];
__device__ int    g_off[CBSZ*(NN1+1)];
__device__ int    g_cur[CBSZ*NN1];
__device__ int    g_esrc[CBSZ*EE];
__device__ float  g_ecoef[CBSZ*EE];
__device__ __half g_embh[BB*SS*ETRD];
__device__ __half g_Wt [HH*ETRD];
__device__ __half g_Wg [NCLS*NLAY*DD*DDP];
__device__ float  g_Who[DD*3];
__device__ float  g_Wto[DD*3];
__device__ float  g_bho[3];
__device__ float  g_bto[3];
__device__ float  g_hW [HWSZ];
__device__ float  g_hT [HWSZ];

// ---------------------------------------------------------------------------
// mma / ldmatrix / cp.async helpers
// ---------------------------------------------------------------------------
__device__ __forceinline__ void mma_f16(float* c, const uint32_t* a, const uint32_t* b) {
    asm volatile(
        "mma.sync.aligned.m16n8k16.row.col.f32.f16.f16.f32 "
        "{%0,%1,%2,%3}, {%4,%5,%6,%7}, {%8,%9}, {%0,%1,%2,%3};"
        : "+f"(c[0]), "+f"(c[1]), "+f"(c[2]), "+f"(c[3])
        : "r"(a[0]), "r"(a[1]), "r"(a[2]), "r"(a[3]), "r"(b[0]), "r"(b[1]));
}

__device__ __forceinline__ void ldsm4(uint32_t* r, uint32_t saddr) {
    asm volatile("ldmatrix.sync.aligned.m8n8.x4.shared.b16 {%0,%1,%2,%3}, [%4];"
                 : "=r"(r[0]), "=r"(r[1]), "=r"(r[2]), "=r"(r[3]) : "r"(saddr));
}

__device__ __forceinline__ uint32_t s2u(const void* p) {
    return (uint32_t)__cvta_generic_to_shared(p);
}

__device__ __forceinline__ void cp16(uint32_t s, const void* g) {
    asm volatile("cp.async.cg.shared.global [%0], [%1], 16;" :: "r"(s), "l"(g));
}
#define CP_COMMIT() asm volatile("cp.async.commit_group;" ::: "memory")
#define CP_WAIT0()  asm volatile("cp.async.wait_group 0;"  ::: "memory")

__device__ __forceinline__ uint32_t pack_h2(float x, float y) {
    __half2 h = __floats2half2_rn(x, y);
    return *(uint32_t*)&h;
}

// ---------------------------------------------------------------------------
// Small helper kernels
// ---------------------------------------------------------------------------
__global__ void k_initmisc(float* __restrict__ deg,
                           float* __restrict__ hW,
                           float* __restrict__ hT) {
    int t = blockIdx.x * blockDim.x + threadIdx.x;
    if (t < DEGSZ) deg[t] = 1.f;
    if (t < HWSZ) { hW[t] = 0.f; hT[t] = 0.f; }
}

__global__ void k_initx0(float* __restrict__ x0,
                         const int* __restrict__ entLab,
                         const float* __restrict__ tbl) {
    int t = blockIdx.x * blockDim.x + threadIdx.x;
    if (t >= XSZ) return;
    int r = t / DD, c = t % DD;
    float v = 0.f;
    if (c < LDD) {
        int i = r % NN1, b = r / NN1;
        if (i == 0) v = tbl[c];
        else {
            int lbl = entLab[b*(NN1-1) + i - 1];
            v = lbl ? tbl[lbl*LDD + c] : 0.f;
        }
    }
    x0[t] = v;
}

__global__ void k_eh(const float4* __restrict__ in, uint2* __restrict__ outp, int n4) {
    int i = blockIdx.x * blockDim.x + threadIdx.x;
    if (i < n4) {
        float4 v = in[i];
        uint2 u;
        u.x = pack_h2(v.x, v.y);
        u.y = pack_h2(v.z, v.w);
        outp[i] = u;
    }
}

__global__ void k_x0h(const float* __restrict__ x0, __half* __restrict__ x0h) {
    int t = blockIdx.x * blockDim.x + threadIdx.x;
    if (t >= MM*DDP) return;
    int r = t / DDP, c = t % DDP;
    x0h[t] = (c < DD) ? __float2half_rn(x0[(size_t)r*DD + c]) : __half(0);
}

__global__ void k_deg(float* __restrict__ deg,
                      const int* __restrict__ ei,
                      const int* __restrict__ ea) {
    int t = blockIdx.x * blockDim.x + threadIdx.x;
    if (t >= BB*EE) return;
    int b = t >> 12, e = t & (EE-1);
    int dst = ei[b*2*EE + EE + e];
    int a   = ea[b*EE + e];
    atomicAdd(&deg[(a*BB + b)*NN1 + dst], 1.f);
}

__global__ void k_off(const float* __restrict__ deg) {
    int cb   = blockIdx.x;
    int lane = threadIdx.x;
    const float* dg = deg + cb*NN1;
    int* off = g_off + cb*(NN1+1);
    int* cur = g_cur + cb*NN1;
    if (lane == 0) off[0] = 0;
    int carry = 0;
    for (int base = 0; base < NN1; base += 32) {
        int i = base + lane;
        int v = (i < NN1) ? (int)dg[i] - 1 : 0;
        int s = v;
        #pragma unroll
        for (int d = 1; d < 32; d <<= 1) {
            int t = __shfl_up_sync(0xffffffffu, s, d);
            if (lane >= d) s += t;
        }
        if (i < NN1) {
            cur[i]   = carry + s - v;
            off[i+1] = carry + s;
        }
        carry += __shfl_sync(0xffffffffu, s, 31);
    }
}

__global__ void k_scatter(const float* __restrict__ deg,
                          const int* __restrict__ ei,
                          const int* __restrict__ ea) {
    int t = blockIdx.x * blockDim.x + threadIdx.x;
    if (t >= BB*EE) return;
    int b = t >> 12, e = t & (EE-1);
    int src = ei[b*2*EE + e];
    int dst = ei[b*2*EE + EE + e];
    int a   = ea[b*EE + e];
    int cb  = a*BB + b;
    const float* dg = deg + cb*NN1;
    float coef = rsqrtf(dg[src]) * rsqrtf(dg[dst]);
    int pos = atomicAdd(&g_cur[cb*NN1 + dst], 1);
    g_esrc [cb*EE + pos] = src;
    g_ecoef[cb*EE + pos] = coef;
}

__global__ void k_th(const float* __restrict__ W, __half* __restrict__ Wt,
                     int K, int N, int KP) {
    const float* Wz  = W  + (size_t)blockIdx.z*K*N;
    __half*      Wtz = Wt + (size_t)blockIdx.z*N*KP;
    __shared__ float t[32][33];
    int k = blockIdx.x*32 + threadIdx.y;
    int n = blockIdx.y*32 + threadIdx.x;
    if (k < K && n < N) t[threadIdx.y][threadIdx.x] = Wz[(size_t)k*N + n];
    __syncthreads();
    int no = blockIdx.y*32 + threadIdx.y;
    int ko = blockIdx.x*32 + threadIdx.x;
    if (no < N && ko < KP)
        Wtz[(size_t)no*KP + ko] = (ko < K) ? __float2half_rn(t[threadIdx.x][threadIdx.y])
                                           : __half(0);
}

// ---------------------------------------------------------------------------
// Big fp16 GEMM (with y-base for split launch), cp.async + LDSM
// ---------------------------------------------------------------------------
#define KC    64
#define RA_LD 72
#define R_SZH (128*RA_LD)
#define RED_SMEM (4*R_SZH*2)

__global__ void __launch_bounds__(512, 1) k_mma_red(
    const __half* __restrict__ A,
    const __half* __restrict__ Bt,
    const float*  __restrict__ bias,
    const int*    __restrict__ entIdx,
    float*        __restrict__ x0,
    int yBase)
{
    extern __shared__ __align__(16) __half smh[];
    __half* sAb[2] = { smh,            smh + R_SZH };
    __half* sBb[2] = { smh + 2*R_SZH,  smh + 3*R_SZH };

    const int tid  = threadIdx.x;
    const int lane = tid & 31;
    const int wid  = tid >> 5;
    const int gr   = lane >> 2;
    const int kq   = lane & 3;
    const int wm   = wid & 3;
    const int wn   = wid >> 2;
    const int row0 = (yBase + blockIdx.y) * 128;
    const int col0 = blockIdx.x * 128;

    const int sr = tid >> 2;
    const int sg = tid & 3;

    const int arow_l = ((lane >> 3) & 1)*8 + (lane & 7);
    const int acol_l = (lane >> 4)*8;
    const int brow_l = (lane >> 4)*8 + (lane & 7);
    const int bcol_l = ((lane >> 3) & 1)*8;
    uint32_t aoff[2], boff[2];
    #pragma unroll
    for (int mi = 0; mi < 2; mi++)
        aoff[mi] = ((wm*32 + mi*16 + arow_l)*RA_LD + acol_l)*2;
    #pragma unroll
    for (int pr = 0; pr < 2; pr++)
        boff[pr] = ((wn*32 + pr*16 + brow_l)*RA_LD + bcol_l)*2;
    uint32_t sAu[2] = { s2u(sAb[0]), s2u(sAb[1]) };
    uint32_t sBu[2] = { s2u(sBb[0]), s2u(sBb[1]) };

    float acc[2][4][4];
    #pragma unroll
    for (int i = 0; i < 2; i++)
        #pragma unroll
        for (int j = 0; j < 4; j++)
            #pragma unroll
            for (int u = 0; u < 4; u++) acc[i][j][u] = 0.f;

    const __half* agp = A  + (size_t)(row0 + sr)*ETRD + sg*16;
    const __half* bgp = Bt + (size_t)(col0 + sr)*ETRD + sg*16;
    const uint32_t sAoff = (sr*RA_LD + sg*16)*2;

    auto ldchunk = [&](int k0, int buf) {
        cp16(sAu[buf] + sAoff,      agp + k0);
        cp16(sAu[buf] + sAoff + 16, agp + k0 + 8);
        cp16(sBu[buf] + sAoff,      bgp + k0);
        cp16(sBu[buf] + sAoff + 16, bgp + k0 + 8);
        CP_COMMIT();
    };
    auto compute = [&](int buf) {
        #pragma unroll
        for (int ks = 0; ks < KC/16; ks++) {
            uint32_t af[2][4], bf[2][4];
            ldsm4(af[0], sAu[buf] + aoff[0] + ks*32);
            ldsm4(af[1], sAu[buf] + aoff[1] + ks*32);
            ldsm4(bf[0], sBu[buf] + boff[0] + ks*32);
            ldsm4(bf[1], sBu[buf] + boff[1] + ks*32);
            #pragma unroll
            for (int mi = 0; mi < 2; mi++) {
                mma_f16(acc[mi][0], af[mi], &bf[0][0]);
                mma_f16(acc[mi][1], af[mi], &bf[0][2]);
                mma_f16(acc[mi][2], af[mi], &bf[1][0]);
                mma_f16(acc[mi][3], af[mi], &bf[1][2]);
            }
        }
    };

    ldchunk(0, 0);
    CP_WAIT0();
    __syncthreads();
    #pragma unroll 1
    for (int ch = 0; ch < ETRD/KC; ch++) {
        if (ch + 1 < ETRD/KC) ldchunk((ch + 1)*KC, (ch + 1) & 1);
        compute(ch & 1);
        if (ch + 1 < ETRD/KC) {
            CP_WAIT0();
            __syncthreads();
        }
    }

    int    nodev[2][2];
    float* basep[2][2];
    #pragma unroll
    for (int mi = 0; mi < 2; mi++)
        #pragma unroll
        for (int h = 0; h < 2; h++) {
            int r  = row0 + wm*32 + mi*16 + gr + h*8;
            int nd = entIdx[r];
            nodev[mi][h] = nd;
            int b = r >> 11;
            basep[mi][h] = x0 + ((size_t)(b*NN1 + nd))*DD + LDD;
        }
    #pragma unroll
    for (int ni = 0; ni < 4; ni++) {
        int c = col0 + wn*32 + ni*8 + kq*2;
        float b0 = __ldg(bias + c), b1 = __ldg(bias + c + 1);
        #pragma unroll
        for (int mi = 0; mi < 2; mi++) {
            #pragma unroll
            for (int h = 0; h < 2; h++) {
                if (nodev[mi][h] == 0) continue;
                float v0 = acc[mi][ni][2*h    ] + b0;
                float v1 = acc[mi][ni][2*h + 1] + b1;
                if (v0 > 0.f) atomicMax((int*)(basep[mi][h] + c),     __float_as_int(v0));
                if (v1 > 0.f) atomicMax((int*)(basep[mi][h] + c + 1), __float_as_int(v1));
            }
        }
    }
}

// ---------------------------------------------------------------------------
// xW GEMM, full cp.async + LDSM, 3 classes via grid.z
// ---------------------------------------------------------------------------
__global__ void __launch_bounds__(512, 1) k_mma_xw(
    const __half* __restrict__ Abase,
    const __half* __restrict__ Wg,
    __half*       __restrict__ Cbase,
    int M, long long strideA, int layer)
{
    const int z = blockIdx.z;
    const __half* A  = Abase + (size_t)z*strideA;
    const __half* Bt = Wg + ((size_t)z*NLAY + layer)*DD*DDP;
    __half* C = Cbase + (size_t)z*MM*DDP;

    extern __shared__ __align__(16) __half smh[];
    __half* sAb[2] = { smh,            smh + R_SZH };
    __half* sBb[2] = { smh + 2*R_SZH,  smh + 3*R_SZH };

    const int tid  = threadIdx.x;
    const int lane = tid & 31;
    const int wid  = tid >> 5;
    const int gr   = lane >> 2;
    const int kq   = lane & 3;
    const int wm   = wid & 3;
    const int wn   = wid >> 2;
    const int row0 = blockIdx.y * 128;
    const int col0 = blockIdx.x * 128;

    const int sr = tid >> 2;
    const int sg = tid & 3;

    const int arow_l = ((lane >> 3) & 1)*8 + (lane & 7);
    const int acol_l = (lane >> 4)*8;
    const int brow_l = (lane >> 4)*8 + (lane & 7);
    const int bcol_l = ((lane >> 3) & 1)*8;
    uint32_t aoff[2], boff[2];
    #pragma unroll
    for (int mi = 0; mi < 2; mi++)
        aoff[mi] = ((wm*32 + mi*16 + arow_l)*RA_LD + acol_l)*2;
    #pragma unroll
    for (int pr = 0; pr < 2; pr++)
        boff[pr] = ((wn*32 + pr*16 + brow_l)*RA_LD + bcol_l)*2;
    uint32_t sAu[2] = { s2u(sAb[0]), s2u(sAb[1]) };
    uint32_t sBu[2] = { s2u(sBb[0]), s2u(sBb[1]) };

    float acc[2][4][4];
    #pragma unroll
    for (int i = 0; i < 2; i++)
        #pragma unroll
        for (int j = 0; j < 4; j++)
            #pragma unroll
            for (int u = 0; u < 4; u++) acc[i][j][u] = 0.f;

    int arow = row0 + sr; if (arow >= M)  arow = M - 1;
    int brow = col0 + sr; if (brow >= DD) brow = DD - 1;
    const __half* agp = A  + (size_t)arow*DDP + sg*16;
    const __half* bgp = Bt + (size_t)brow*DDP + sg*16;
    const uint32_t sAoff = (sr*RA_LD + sg*16)*2;

    auto ldchunk = [&](int k0, int buf) {
        cp16(sAu[buf] + sAoff,      agp + k0);
        cp16(sAu[buf] + sAoff + 16, agp + k0 + 8);
        cp16(sBu[buf] + sAoff,      bgp + k0);
        cp16(sBu[buf] + sAoff + 16, bgp + k0 + 8);
        CP_COMMIT();
    };
    auto compute = [&](int buf) {
        #pragma unroll
        for (int ks = 0; ks < KC/16; ks++) {
            uint32_t af[2][4], bf[2][4];
            ldsm4(af[0], sAu[buf] + aoff[0] + ks*32);
            ldsm4(af[1], sAu[buf] + aoff[1] + ks*32);
            ldsm4(bf[0], sBu[buf] + boff[0] + ks*32);
            ldsm4(bf[1], sBu[buf] + boff[1] + ks*32);
            #pragma unroll
            for (int mi = 0; mi < 2; mi++) {
                mma_f16(acc[mi][0], af[mi], &bf[0][0]);
                mma_f16(acc[mi][1], af[mi], &bf[0][2]);
                mma_f16(acc[mi][2], af[mi], &bf[1][0]);
                mma_f16(acc[mi][3], af[mi], &bf[1][2]);
            }
        }
    };

    ldchunk(0, 0);
    CP_WAIT0();
    __syncthreads();
    #pragma unroll 1
    for (int ch = 0; ch < DDP/KC; ch++) {
        if (ch + 1 < DDP/KC) ldchunk((ch + 1)*KC, (ch + 1) & 1);
        compute(ch & 1);
        if (ch + 1 < DDP/KC) {
            CP_WAIT0();
            __syncthreads();
        }
    }

    #pragma unroll
    for (int mi = 0; mi < 2; mi++) {
        #pragma unroll
        for (int h = 0; h < 2; h++) {
            int gm = row0 + wm*32 + mi*16 + gr + h*8;
            if (gm >= M) continue;
            #pragma unroll
            for (int ni = 0; ni < 4; ni++) {
                int gn = col0 + wn*32 + ni*8 + kq*2;
                if (gn < DD) {
                    *(uint32_t*)(C + (size_t)gm*DDP + gn) =
                        pack_h2(acc[mi][ni][2*h], acc[mi][ni][2*h + 1]);
                }
            }
        }
    }
}

// ---------------------------------------------------------------------------
// Sparse GCN aggregation, warp-per-dst (8 dst/block), fp16 h, grid.z classes.
// ---------------------------------------------------------------------------
#define NH2  (DD/2)     // 264
#define NH2P (DDP/2)    // 288

__global__ void __launch_bounds__(256) k_spmm(
    const __half* __restrict__ hbase,
    __half* __restrict__ xbH,
    const float* __restrict__ deg,
    const float* __restrict__ bgcn,
    const float* __restrict__ Who,
    const float* __restrict__ Wto,
    float* __restrict__ hW,
    float* __restrict__ hT,
    int layer)
{
    int wid  = threadIdx.x >> 5;
    int lane = threadIdx.x & 31;
    int dst  = blockIdx.x*8 + wid;
    if (dst >= NN1) return;
    int b   = blockIdx.y;
    int cls = blockIdx.z;
    int cb  = cls*BB + b;

    const float* bias = bgcn + (size_t)(cls*NLAY + layer)*DD;
    const __half* hb  = hbase + ((size_t)cls*MM + (size_t)b*NN1)*DDP;

    const int* off = g_off + cb*(NN1+1);
    int e0 = off[dst], e1 = off[dst+1];
    const int*   es = g_esrc  + cb*EE;
    const float* ec = g_ecoef + cb*EE;

    float2 acc[9];
    #pragma unroll
    for (int it = 0; it < 9; it++) acc[it] = make_float2(0.f, 0.f);

    for (int e = e0; e < e1; e++) {
        int   src = es[e];
        float w   = ec[e];
        const __half2* hr = (const __half2*)(hb + (size_t)src*DDP);
        #pragma unroll
        for (int it = 0; it < 9; it++) {
            int j = lane + it*32;
            if (j < NH2) {
                float2 x = __half22float2(hr[j]);
                acc[it].x += w * x.x;
                acc[it].y += w * x.y;
            }
        }
    }

    float dinv = 1.f / deg[cb*NN1 + dst];
    const __half2* hd = (const __half2*)(hb + (size_t)dst*DDP);

    float2 v[9];
    #pragma unroll
    for (int it = 0; it < 9; it++) {
        int j = lane + it*32;
        if (j < NH2) {
            float2 s = __half22float2(hd[j]);
            float2 bi = *(const float2*)(bias + 2*j);
            v[it].x = acc[it].x + s.x*dinv + bi.x;
            v[it].y = acc[it].y + s.y*dinv + bi.y;
        } else {
            v[it] = make_float2(0.f, 0.f);
        }
    }

    if (layer == 0) {
        __half* xo = xbH + ((size_t)cls*MM + (size_t)b*NN1 + dst)*DDP;
        #pragma unroll
        for (int it = 0; it < 9; it++) {
            int j = lane + it*32;
            *(uint32_t*)(xo + 2*j) = pack_h2(v[it].x, v[it].y);
        }
        return;
    }

    float lw[3] = {0.f, 0.f, 0.f}, lt[3] = {0.f, 0.f, 0.f};
    #pragma unroll
    for (int it = 0; it < 9; it++) {
        int j = lane + it*32;
        if (j < NH2) {
            #pragma unroll
            for (int c = 0; c < 3; c++) {
                lw[c] += v[it].x*Who[(2*j)*3 + c] + v[it].y*Who[(2*j + 1)*3 + c];
                lt[c] += v[it].x*Wto[(2*j)*3 + c] + v[it].y*Wto[(2*j + 1)*3 + c];
            }
        }
    }
    #pragma unroll
    for (int d = 16; d > 0; d >>= 1) {
        #pragma unroll
        for (int c = 0; c < 3; c++) {
            lw[c] += __shfl_down_sync(0xffffffffu, lw[c], d);
            lt[c] += __shfl_down_sync(0xffffffffu, lt[c], d);
        }
    }
    if (lane == 0) {
        int idx = (b*NN1 + dst)*3;
        #pragma unroll
        for (int c = 0; c < 3; c++) {
            atomicAdd(&hW[idx + c], lw[c] * (1.f/3.f));
            atomicAdd(&hT[idx + c], lt[c] * (1.f/3.f));
        }
    }
}

// ---------------------------------------------------------------------------
// Collapsed head/tail weights + logits
// ---------------------------------------------------------------------------
__global__ void k_ho(const float* __restrict__ W_head, const float* __restrict__ W_tail,
                     const float* __restrict__ W_out,
                     const float* __restrict__ b_head, const float* __restrict__ b_tail,
                     float* __restrict__ Who, float* __restrict__ Wto,
                     float* __restrict__ bho, float* __restrict__ bto) {
    int t = blockIdx.x * blockDim.x + threadIdx.x;
    if (t < 2*DD*3) {
        int which = t / (DD*3), rc = t % (DD*3), r = rc / 3, c = rc % 3;
        const float* W = which ? W_tail : W_head;
        float acc = 0.f;
        for (int j = 0; j < DD; j++) acc += W[r*DD + j] * W_out[j*3 + c];
        (which ? Wto : Who)[r*3 + c] = acc;
    } else if (t < 2*DD*3 + 6) {
        int u = t - 2*DD*3, which = u / 3, c = u % 3;
        const float* bb = which ? b_tail : b_head;
        float acc = 0.f;
        for (int j = 0; j < DD; j++) acc += bb[j] * W_out[j*3 + c];
        (which ? bto : bho)[c] = acc;
    }
}

__global__ void k_logits(const int* __restrict__ cands,
                         const float* __restrict__ hW, const float* __restrict__ hT,
                         const float* __restrict__ bho, const float* __restrict__ bto,
                         const float* __restrict__ b_out,
                         float* __restrict__ out) {
    int t = blockIdx.x * blockDim.x + threadIdx.x;
    const int TOT = BB*NN1*(NN1-1)*3;
    if (t >= TOT) return;
    int c = t % 3;
    int j = (t / 3) & 255;
    int i = (t / (3*256)) % NN1;
    int b = t / (3*256*NN1);
    int m = cands[((long long)(b*NN1 + i))*NN1 + j + 1];
    float v = b_out[c];
    if (m) v += hW[(b*NN1 + i)*3 + c] + bho[c] + hT[(b*NN1 + j + 1)*3 + c] + bto[c];
    out[t] = v;
}

// ---------------------------------------------------------------------------
// Launch (multi-stream fork/join, graph-capturable) — R15 schedule
// ---------------------------------------------------------------------------
extern "C" void kernel_launch(void* const* d_in, const int* in_sizes, int n_in,
                              void* d_out, int out_size) {
    const float* emb     = (const float*)d_in[0];
    const int*   entIdx  = (const int*)  d_in[1];
    const int*   entLab  = (const int*)  d_in[2];
    const int*   edgeIdx = (const int*)  d_in[3];
    const int*   edgeAttr= (const int*)  d_in[4];
    const int*   cands   = (const int*)  d_in[5];
    const float* W_red   = (const float*)d_in[6];
    const float* b_red   = (const float*)d_in[7];
    const float* tbl     = (const float*)d_in[8];
    const float* W_gcn   = (const float*)d_in[9];
    const float* b_gcn   = (const float*)d_in[10];
    const float* W_head  = (const float*)d_in[11];
    const float* b_head  = (const float*)d_in[12];
    const float* W_tail  = (const float*)d_in[13];
    const float* b_tail  = (const float*)d_in[14];
    const float* W_out   = (const float*)d_in[15];
    const float* b_out   = (const float*)d_in[16];
    float* out = (float*)d_out;

    static float *px0=nullptr, *pdeg,
                 *pWho, *pWto, *pbho, *pbto, *phW, *phT;
    static __half *pWt, *pWg, *pEh, *px0h, *pxb16, *phc;
    static cudaStream_t s2 = nullptr, s3 = nullptr;
    static cudaEvent_t evFork = nullptr, evJ2 = nullptr, evJ3a = nullptr, evJ3b = nullptr;
    static bool attr_set = false;
    if (!px0) {
        cudaGetSymbolAddress((void**)&px0,   g_x0);
        cudaGetSymbolAddress((void**)&px0h,  g_x0h);
        cudaGetSymbolAddress((void**)&phc,   g_hc);
        cudaGetSymbolAddress((void**)&pxb16, g_xb16);
        cudaGetSymbolAddress((void**)&pdeg,  g_deg);
        cudaGetSymbolAddress((void**)&pWt,   g_Wt);
        cudaGetSymbolAddress((void**)&pWg,   g_Wg);
        cudaGetSymbolAddress((void**)&pEh,   g_embh);
        cudaGetSymbolAddress((void**)&pWho,  g_Who);
        cudaGetSymbolAddress((void**)&pWto,  g_Wto);
        cudaGetSymbolAddress((void**)&pbho,  g_bho);
        cudaGetSymbolAddress((void**)&pbto,  g_bto);
        cudaGetSymbolAddress((void**)&phW,   g_hW);
        cudaGetSymbolAddress((void**)&phT,   g_hT);
        cudaStreamCreateWithFlags(&s2, cudaStreamNonBlocking);
        cudaStreamCreateWithFlags(&s3, cudaStreamNonBlocking);
        cudaEventCreateWithFlags(&evFork, cudaEventDisableTiming);
        cudaEventCreateWithFlags(&evJ2,   cudaEventDisableTiming);
        cudaEventCreateWithFlags(&evJ3a,  cudaEventDisableTiming);
        cudaEventCreateWithFlags(&evJ3b,  cudaEventDisableTiming);
    }
    if (!attr_set) {
        cudaFuncSetAttribute(k_mma_red, cudaFuncAttributeMaxDynamicSharedMemorySize, RED_SMEM);
        cudaFuncSetAttribute(k_mma_xw,  cudaFuncAttributeMaxDynamicSharedMemorySize, RED_SMEM);
        attr_set = true;
    }

    auto blocks = [](int n) { return (n + 255) / 256; };
    const int EH_TOT4  = BB*SS*ETRD/4;
    const int EH_HALF4 = EH_TOT4/2;

    // ---- fork ----
    cudaEventRecord(evFork, 0);
    cudaStreamWaitEvent(s2, evFork, 0);
    cudaStreamWaitEvent(s3, evFork, 0);

    // s2: CSR chain + Wg transpose + collapsed head/tail
    k_initmisc<<<blocks(HWSZ), 256, 0, s2>>>(pdeg, phW, phT);
    k_deg     <<<blocks(BB*EE), 256, 0, s2>>>(pdeg, edgeIdx, edgeAttr);
    k_off     <<<CBSZ, 32, 0, s2>>>(pdeg);
    k_scatter <<<blocks(BB*EE), 256, 0, s2>>>(pdeg, edgeIdx, edgeAttr);
    {
        dim3 bl(32, 32);
        k_th<<<dim3(DDP/32, (DD+31)/32, NCLS*NLAY), bl, 0, s2>>>(W_gcn, pWg, DD, DD, DDP);
    }
    k_ho<<<blocks(2*DD*3 + 6), 256, 0, s2>>>(W_head, W_tail, W_out, b_head, b_tail,
                                             pWho, pWto, pbho, pbto);
    cudaEventRecord(evJ2, s2);

    // s3: x0 init + W_red transpose (gates first GEMM half) then emb half 2
    k_initx0<<<blocks(XSZ), 256, 0, s3>>>(px0, entLab, tbl);
    {
        dim3 bl(32, 32);
        k_th<<<dim3(ETRD/32, HH/32, 1), bl, 0, s3>>>(W_red, pWt, ETRD, HH, ETRD);
    }
    cudaEventRecord(evJ3a, s3);
    k_eh<<<blocks(EH_HALF4), 256, 0, s3>>>((const float4*)emb + EH_HALF4,
                                           (uint2*)pEh + EH_HALF4, EH_HALF4);
    cudaEventRecord(evJ3b, s3);

    // main: emb half 1 convert -> first GEMM half; second half after join
    k_eh<<<blocks(EH_HALF4), 256>>>((const float4*)emb, (uint2*)pEh, EH_HALF4);
    cudaStreamWaitEvent(0, evJ3a, 0);     // x0 + Wt ready
    {
        dim3 g(HH/128, 128);              // y-blocks [0,128)
        k_mma_red<<<g, 512, RED_SMEM>>>(pEh, pWt, b_red, entIdx, px0, 0);
    }
    cudaStreamWaitEvent(0, evJ3b, 0);     // emb half 2 converted
    {
        dim3 g(HH/128, 128);              // y-blocks [128,256)
        k_mma_red<<<g, 512, RED_SMEM>>>(pEh, pWt, b_red, entIdx, px0, 128);
    }
    k_x0h<<<blocks(MM*DDP), 256>>>(px0, px0h);

    cudaStreamWaitEvent(0, evJ2, 0);      // CSR, Wg, Who/Wto, hW/hT ready

    // GCN: 2 layers, all 3 classes per launch; layer 1 fuses head/tail proj
    {
        dim3 gx((DD + 127)/128, (MM + 127)/128, NCLS);
        dim3 gs((NN1 + 7)/8, BB, NCLS);
        k_mma_xw<<<gx, 512, RED_SMEM>>>(px0h, pWg, phc, MM, 0LL, 0);
        k_spmm  <<<gs, 256>>>(phc, pxb16, pdeg, b_gcn, pWho, pWto, phW, phT, 0);
        k_mma_xw<<<gx, 512, RED_SMEM>>>(pxb16, pWg, phc, MM, (long long)MM*DDP, 1);
        k_spmm  <<<gs, 256>>>(phc, nullptr, pdeg, b_gcn, pWho, pWto, phW, phT, 1);
    }

    // logits
    k_logits<<<blocks(BB*NN1*(NN1-1)*3), 256>>>(cands, phW, phT, pbho, pbto, b_out, out);
}